// round 1
// baseline (speedup 1.0000x reference)
#include <cuda_runtime.h>

// TritonDualLIF: x [T=16,B=32,N=196,C=512] f32, decay scalar.
// Recurrence per element: v = d*v + x[t]; vpool[t,b,c] = mean_n(v); s = (v>=1); v = s?0:v.
// Output: spikes [T,B,N,C] followed by vpool [T,B,C] in d_out.

#define T_ 16
#define B_ 32
#define N_ 196
#define C_ 512
#define NLANES 8
#define JMAX 25   // ceil(196/8)

__global__ __launch_bounds__(256, 3)
void lif_dual_kernel(const float* __restrict__ x,
                     const float* __restrict__ decay,
                     float* __restrict__ out) {
    const int tx = threadIdx.x;          // c within 32-wide tile
    const int ty = threadIdx.y;          // n lane, 0..7
    const int cblk = blockIdx.x;         // 0..15
    const int b = blockIdx.y;            // 0..31
    const int c = cblk * 32 + tx;
    const float d = decay[0];

    float* __restrict__ spikes = out;
    float* __restrict__ vpool  = out + (size_t)T_ * B_ * N_ * C_;

    __shared__ float red[NLANES][32];

    float v[JMAX];
#pragma unroll
    for (int j = 0; j < JMAX; ++j) v[j] = 0.0f;

    // base offset for (b, n=ty, c) at t=0
    const size_t bbase = (size_t)b * N_ * C_ + (size_t)ty * C_ + c;

    for (int t = 0; t < T_; ++t) {
        const size_t tbase = (size_t)t * B_ * N_ * C_ + bbase;
        float partial = 0.0f;
#pragma unroll
        for (int j = 0; j < JMAX; ++j) {
            const int n = ty + j * NLANES;
            if (n < N_) {
                const size_t idx = tbase + (size_t)j * (NLANES * C_);
                const float xv = x[idx];
                const float vv = fmaf(d, v[j], xv);
                partial += vv;                       // pre-reset membrane for pooling
                const bool fire = (vv >= 1.0f);
                spikes[idx] = fire ? 1.0f : 0.0f;
                v[j] = fire ? 0.0f : vv;             // hard reset
            }
        }
        red[ty][tx] = partial;
        __syncthreads();
        if (ty == 0) {
            float sum = 0.0f;
#pragma unroll
            for (int k = 0; k < NLANES; ++k) sum += red[k][tx];
            vpool[(size_t)t * B_ * C_ + (size_t)b * C_ + c] = sum * (1.0f / (float)N_);
        }
        __syncthreads();   // protect red[] before next timestep's store
    }
}

extern "C" void kernel_launch(void* const* d_in, const int* in_sizes, int n_in,
                              void* d_out, int out_size) {
    const float* x     = (const float*)d_in[0];
    const float* decay = (const float*)d_in[1];
    float* out = (float*)d_out;

    dim3 block(32, NLANES);         // 256 threads
    dim3 grid(C_ / 32, B_);         // 16 x 32 = 512 blocks
    lif_dual_kernel<<<grid, block>>>(x, decay, out);
}